// round 8
// baseline (speedup 1.0000x reference)
#include <cuda_runtime.h>
#include <limits.h>

// Problem constants (fixed by setup_inputs)
#define N_PERK 16384
#define NQK    4096      // B * M_PER
#define CINF   16
#define NS0    16
#define NS1    32
#define NT0    65536     // NQK * NS0
#define NT1    131072    // NQK * NS1

// channel offsets into the 144-wide BN stat arrays
#define OFF_S0L1 0
#define OFF_S0L2 16
#define OFF_S1L1 48
#define OFF_S1L2 80

#define GRIDR  10
#define NCELLS 1000
#define CAP1   768
#define CAP0   192

#define NB_L1  384   // l1stats blocks (256 scale1 + 128 scale0)
#define NB_L2  768   // l2big blocks  (512 scale1 + 256 scale0)

// ---------------- scratch (device globals; no allocation allowed) ----------
struct Scratch {
    int      cellcnt[2016];
    int      cellofs[2016];
    double   sum[144];
    double   sqs[144];
    unsigned ctr1, ctr2;
};
__device__ Scratch d_scr;
__device__ int    d_cellstart[2048];
__device__ float4 d_pts4 [2 * N_PERK]; // original order: (x,y,z,|p|^2)
__device__ float4 d_cpts4[2 * N_PERK]; // cell-sorted
__device__ int    d_cidx [2 * N_PERK]; // cell-sorted original index
__device__ float  d_g0 [19 * NT0];
__device__ float  d_g1 [19 * NT1];
__device__ float  d_mx [NQK * 96];     // per-(query,col) max of pre-BN l2
__device__ float  d_mn [NQK * 96];     // per-(query,col) min
__device__ float  d_p1s[48], d_p1b[48]; // layer1 BN params: [0,32)=s1, [32,48)=s0
__device__ float  d_p2s[96], d_p2b[96]; // layer2 BN params per output column

// ---------------- kernel 0: pack points + count cells -----------------------
__global__ void prep_count_kernel(const float* __restrict__ xyz)
{
    int i = blockIdx.x * blockDim.x + threadIdx.x;
    if (i >= 2 * N_PERK) return;
    float x = xyz[i*3+0], y = xyz[i*3+1], z = xyz[i*3+2];
    d_pts4[i] = make_float4(x, y, z, fmaf(z, z, fmaf(y, y, x*x)));
    int cx = min(GRIDR-1, max(0, (int)(x * 10.f)));
    int cy = min(GRIDR-1, max(0, (int)(y * 10.f)));
    int cz = min(GRIDR-1, max(0, (int)(z * 10.f)));
    int cell = (i >> 14) * NCELLS + (cz * GRIDR + cy) * GRIDR + cx;
    atomicAdd(&d_scr.cellcnt[cell], 1);
}

// ---------------- kernel 1: fused scan + scatter ----------------------------
__global__ void __launch_bounds__(256) scatter_kernel()
{
    __shared__ int sstart[2048];
    __shared__ int warpsum[8], warpbase[8];
    int t = threadIdx.x;
    int lane = t & 31, w = t >> 5;

    int v[8];
    int loc = 0;
    int base = t * 8;
    #pragma unroll
    for (int j = 0; j < 8; j++) {
        int k = base + j;
        int c = (k < 2 * NCELLS) ? d_scr.cellcnt[k] : 0;
        v[j] = loc;
        loc += c;
    }
    int inc = loc;
    #pragma unroll
    for (int d = 1; d < 32; d <<= 1) {
        int x = __shfl_up_sync(0xffffffffu, inc, d);
        if (lane >= d) inc += x;
    }
    if (lane == 31) warpsum[w] = inc;
    __syncthreads();
    if (t == 0) {
        int s = 0;
        #pragma unroll
        for (int i = 0; i < 8; i++) { warpbase[i] = s; s += warpsum[i]; }
    }
    __syncthreads();
    int tbase = warpbase[w] + (inc - loc);
    #pragma unroll
    for (int j = 0; j < 8; j++)
        sstart[base + j] = tbase + v[j];
    __syncthreads();

    if (blockIdx.x == 0)
        for (int k = t; k <= 2 * NCELLS; k += 256)
            d_cellstart[k] = (k < 2048) ? sstart[k] : 0;

    int i = blockIdx.x * 256 + t;
    if (i < 2 * N_PERK) {
        float4 p = d_pts4[i];
        int cx = min(GRIDR-1, max(0, (int)(p.x * 10.f)));
        int cy = min(GRIDR-1, max(0, (int)(p.y * 10.f)));
        int cz = min(GRIDR-1, max(0, (int)(p.z * 10.f)));
        int cell = (i >> 14) * NCELLS + (cz * GRIDR + cy) * GRIDR + cx;
        int pos = sstart[cell] + atomicAdd(&d_scr.cellofs[cell], 1);
        d_cpts4[pos] = p;
        d_cidx[pos]  = i & (N_PERK - 1);
    }
}

// ---------------- select k smallest indices from cand[cnt] -----------------
__device__ __forceinline__ int select_k(const int* __restrict__ cand, int cnt,
                                        const int* __restrict__ bc,
                                        int* __restrict__ sel2,
                                        int* __restrict__ fin,
                                        int k, int lane, unsigned low)
{
    if (cnt <= k) {
        for (int i = lane; i < cnt; i += 32) fin[i] = cand[i];
        return cnt;
    }
    int p = bc[lane];
    #pragma unroll
    for (int d = 1; d < 32; d <<= 1) {
        int t = __shfl_up_sync(0xffffffffu, p, d);
        if (lane >= d) p += t;
    }
    unsigned mk = __ballot_sync(0xffffffffu, p >= k);
    int bstar = __ffs(mk) - 1;
    int base  = (bstar > 0) ? __shfl_sync(0xffffffffu, p, bstar - 1) : 0;
    int need  = k - base;
    int B0 = bstar << 9, B1 = (bstar + 1) << 9;

    int n_auto = 0, n_mid = 0;
    for (int i0 = 0; i0 < cnt; i0 += 32) {
        int i = i0 + lane;
        int v = (i < cnt) ? cand[i] : INT_MAX;
        bool a = (v < B0);
        bool m = (v >= B0) && (v < B1);
        unsigned ma = __ballot_sync(0xffffffffu, a);
        unsigned mm = __ballot_sync(0xffffffffu, m);
        if (a) fin[n_auto + __popc(ma & low)] = v;
        else if (m) {
            int pos = n_mid + __popc(mm & low);
            if (pos < 64) sel2[pos] = v;
        }
        n_auto += __popc(ma);
        n_mid  += __popc(mm);
    }
    if (n_mid > 64) n_mid = 64;
    __syncwarp();

    int last = -1;
    for (int j = 0; j < need; j++) {
        int v = INT_MAX;
        for (int i = lane; i < n_mid; i += 32) {
            int x = sel2[i];
            if (x > last && x < v) v = x;
        }
        #pragma unroll
        for (int d = 16; d; d >>= 1)
            v = min(v, __shfl_xor_sync(0xffffffffu, v, d));
        fin[base + j] = v;
        last = v;
    }
    return k;
}

// ---------------- kernel 2: block-per-query dual-scale ball query ----------
__global__ void __launch_bounds__(128) bq_block_kernel(
    const float* __restrict__ nxyz, const float* __restrict__ feat)
{
    __shared__ int cand1[CAP1], cand0[CAP0];
    __shared__ int bc1[32], bc0[32];
    __shared__ int sel2a[64], sel2b[64];
    __shared__ int fin1[NS1], fin0[NS0];
    __shared__ int scnt1, scnt0, slmin1, slmin0, m1n_s, m0n_s;

    int tid  = threadIdx.x;
    int wid  = tid >> 5;
    int lane = tid & 31;
    unsigned low = (1u << lane) - 1u;

    int q = blockIdx.x;
    int b = q >> 11;
    int nbase = b << 14;

    if (tid < 32) { bc1[tid] = 0; bc0[tid] = 0; }
    if (tid == 0) {
        scnt1 = 0; scnt0 = 0;
        slmin1 = INT_MAX; slmin0 = INT_MAX;
    }
    __syncthreads();

    float qx = nxyz[q*3+0], qy = nxyz[q*3+1], qz = nxyz[q*3+2];
    float q2 = fmaf(qz, qz, fmaf(qy, qy, qx*qx));

    int cy = min(GRIDR-1, max(0, (int)(qy * 10.f)));
    int cz = min(GRIDR-1, max(0, (int)(qz * 10.f)));
    int zlo = max(0, cz-2), zhi = min(GRIDR-1, cz+2);
    int ylo = max(0, cy-2), yhi = min(GRIDR-1, cy+2);
    int nz = zhi - zlo + 1, ny = yhi - ylo + 1;

    const float RP2 = 0.04f + 1e-4f;
    int lmin1 = INT_MAX, lmin0 = INT_MAX;

    for (int ri = wid; ri < nz * ny; ri += 4) {
        int zz = zlo + ri / ny;
        int yy = ylo + ri % ny;
        float dz = fmaxf(0.f, fmaxf(zz * 0.1f - qz, qz - (zz+1) * 0.1f));
        float dy = fmaxf(0.f, fmaxf(yy * 0.1f - qy, qy - (yy+1) * 0.1f));
        float r2 = fmaf(dy, dy, dz * dz);
        if (r2 >= RP2) continue;
        float dxm = sqrtf(RP2 - r2);
        int xlo = max(0, (int)floorf((qx - dxm) * 10.f));
        int xhi = min(GRIDR-1, (int)floorf((qx + dxm) * 10.f));
        if (xlo > xhi) continue;
        int row = b * NCELLS + (zz * GRIDR + yy) * GRIDR;
        int s = d_cellstart[row + xlo];
        int e = d_cellstart[row + xhi + 1];
        for (int i0 = s; i0 < e; i0 += 32) {
            int i = i0 + lane;
            bool ok1 = false, ok0 = false;
            int idx = 0;
            if (i < e) {
                float4 p = d_cpts4[i];
                idx = d_cidx[i];
                float dt = fmaf(qz, p.z, fmaf(qy, p.y, qx*p.x));
                float d2 = fmaf(-2.f, dt, q2 + p.w);
                ok1 = d2 < 0.04f;
                ok0 = d2 < 0.01f;
            }
            unsigned m1 = __ballot_sync(0xffffffffu, ok1);
            unsigned m0 = __ballot_sync(0xffffffffu, ok0);
            if (m1) {
                int bpos = 0;
                if (lane == 0) bpos = atomicAdd(&scnt1, __popc(m1));
                bpos = __shfl_sync(0xffffffffu, bpos, 0);
                if (ok1) {
                    lmin1 = min(lmin1, idx);
                    int pos = bpos + __popc(m1 & low);
                    if (pos < CAP1) {
                        cand1[pos] = idx;
                        atomicAdd(&bc1[idx >> 9], 1);
                    }
                }
            }
            if (m0) {
                int bpos = 0;
                if (lane == 0) bpos = atomicAdd(&scnt0, __popc(m0));
                bpos = __shfl_sync(0xffffffffu, bpos, 0);
                if (ok0) {
                    lmin0 = min(lmin0, idx);
                    int pos = bpos + __popc(m0 & low);
                    if (pos < CAP0) {
                        cand0[pos] = idx;
                        atomicAdd(&bc0[idx >> 9], 1);
                    }
                }
            }
        }
    }
    #pragma unroll
    for (int d = 16; d; d >>= 1) {
        lmin1 = min(lmin1, __shfl_xor_sync(0xffffffffu, lmin1, d));
        lmin0 = min(lmin0, __shfl_xor_sync(0xffffffffu, lmin0, d));
    }
    if (lane == 0) {
        atomicMin(&slmin1, lmin1);
        atomicMin(&slmin0, lmin0);
    }
    __syncthreads();

    if (wid == 0) {
        int n = select_k(cand1, min(scnt1, CAP1), bc1, sel2a, fin1, NS1, lane, low);
        if (lane == 0) m1n_s = n;
    } else if (wid == 1) {
        int n = select_k(cand0, min(scnt0, CAP0), bc0, sel2b, fin0, NS0, lane, low);
        if (lane == 0) m0n_s = n;
    }
    __syncthreads();

    if (wid == 0) {   // scale-1 grouping
        int m1n = m1n_s;
        int sidx = q * NS1 + lane;
        float g[19];
        if (m1n == 0) {
            #pragma unroll
            for (int c = 0; c < 19; c++) g[c] = 0.f;
        } else {
            int id = (lane < m1n) ? fin1[lane] : slmin1;
            float4 p = d_pts4[nbase + id];
            g[0] = p.x - qx; g[1] = p.y - qy; g[2] = p.z - qz;
            const float4* f = (const float4*)(feat + (size_t)(nbase + id) * CINF);
            float4 f0 = f[0], f1 = f[1], f2 = f[2], f3 = f[3];
            g[3]=f0.x; g[4]=f0.y; g[5]=f0.z; g[6]=f0.w;
            g[7]=f1.x; g[8]=f1.y; g[9]=f1.z; g[10]=f1.w;
            g[11]=f2.x; g[12]=f2.y; g[13]=f2.z; g[14]=f2.w;
            g[15]=f3.x; g[16]=f3.y; g[17]=f3.z; g[18]=f3.w;
        }
        #pragma unroll
        for (int c = 0; c < 19; c++) d_g1[c * NT1 + sidx] = g[c];
    } else if (wid == 1 && lane < NS0) {   // scale-0 grouping
        int m0n = m0n_s;
        int sidx = q * NS0 + lane;
        float g[19];
        if (m0n == 0) {
            #pragma unroll
            for (int c = 0; c < 19; c++) g[c] = 0.f;
        } else {
            int id = (lane < m0n) ? fin0[lane] : slmin0;
            float4 p = d_pts4[nbase + id];
            g[0] = p.x - qx; g[1] = p.y - qy; g[2] = p.z - qz;
            const float4* f = (const float4*)(feat + (size_t)(nbase + id) * CINF);
            float4 f0 = f[0], f1 = f[1], f2 = f[2], f3 = f[3];
            g[3]=f0.x; g[4]=f0.y; g[5]=f0.z; g[6]=f0.w;
            g[7]=f1.x; g[8]=f1.y; g[9]=f1.z; g[10]=f1.w;
            g[11]=f2.x; g[12]=f2.y; g[13]=f2.z; g[14]=f2.w;
            g[15]=f3.x; g[16]=f3.y; g[17]=f3.z; g[18]=f3.w;
        }
        #pragma unroll
        for (int c = 0; c < 19; c++) d_g0[c * NT0 + sidx] = g[c];
    }
}

// ---------------- layer-1 stats body (no store), SPT=2 ---------------------
template<int COUT>
__device__ __forceinline__ void l1stats_body(
    int bid, const float* __restrict__ in, int ntot,
    const float* __restrict__ W,
    float* __restrict__ sW, float* __restrict__ shm, float* __restrict__ shq,
    int off)
{
    const int CINP = 20;
    for (int i = threadIdx.x; i < COUT * CINP; i += 256) {
        int o = i / CINP, c = i % CINP;
        sW[i] = (c < 19) ? W[o * 19 + c] : 0.f;
    }
    for (int i = threadIdx.x; i < COUT; i += 256) { shm[i] = 0.f; shq[i] = 0.f; }
    __syncthreads();

    int s    = (bid * 256 + threadIdx.x) * 2;
    int lane = threadIdx.x & 31;

    float2 x[CINP];
    #pragma unroll
    for (int c = 0; c < CINP; c++)
        x[c] = (c < 19) ? *(const float2*)&in[(size_t)c * ntot + s]
                        : make_float2(0.f, 0.f);

    const float4* sW4 = (const float4*)sW;
    #pragma unroll
    for (int o = 0; o < COUT; o++) {
        float ax = 0.f, ay = 0.f;
        #pragma unroll
        for (int c4 = 0; c4 < CINP / 4; c4++) {
            float4 wv = sW4[o * (CINP / 4) + c4];
            ax = fmaf(x[c4*4+0].x, wv.x, ax); ay = fmaf(x[c4*4+0].y, wv.x, ay);
            ax = fmaf(x[c4*4+1].x, wv.y, ax); ay = fmaf(x[c4*4+1].y, wv.y, ay);
            ax = fmaf(x[c4*4+2].x, wv.z, ax); ay = fmaf(x[c4*4+2].y, wv.z, ay);
            ax = fmaf(x[c4*4+3].x, wv.w, ax); ay = fmaf(x[c4*4+3].y, wv.w, ay);
        }
        float sm = ax + ay;
        float sq = fmaf(ax, ax, ay * ay);
        #pragma unroll
        for (int d = 16; d; d >>= 1) {
            sm += __shfl_down_sync(0xffffffffu, sm, d);
            sq += __shfl_down_sync(0xffffffffu, sq, d);
        }
        if (lane == 0) { atomicAdd(&shm[o], sm); atomicAdd(&shq[o], sq); }
    }
    __syncthreads();
    if (threadIdx.x < COUT) {
        atomicAdd(&d_scr.sum[off + threadIdx.x], (double)shm[threadIdx.x]);
        atomicAdd(&d_scr.sqs[off + threadIdx.x], (double)shq[threadIdx.x]);
    }
}

// ---------------- kernel 3: layer-1 stats (both scales); last block → params
__global__ void __launch_bounds__(256) l1stats_kernel(
    const float* __restrict__ w10, const float* __restrict__ w00,
    const float* __restrict__ g10, const float* __restrict__ b10,
    const float* __restrict__ g00, const float* __restrict__ b00)
{
    __shared__ __align__(16) float sW[32 * 20];
    __shared__ float shm[32], shq[32];
    __shared__ int is_last;

    if (blockIdx.x < 256)
        l1stats_body<32>(blockIdx.x, d_g1, NT1, w10, sW, shm, shq, OFF_S1L1);
    else
        l1stats_body<16>(blockIdx.x - 256, d_g0, NT0, w00, sW, shm, shq, OFF_S0L1);

    if (threadIdx.x == 0) {
        __threadfence();
        unsigned d = atomicAdd(&d_scr.ctr1, 1u);
        is_last = (d == NB_L1 - 1);
    }
    __syncthreads();
    if (is_last && threadIdx.x < 48) {
        int t = threadIdx.x;
        int off; float pN, gam, bet;
        if (t < 32) { off = OFF_S1L1 + t; pN = (float)NT1; gam = g10[t]; bet = b10[t]; }
        else        { off = OFF_S0L1 + t - 32; pN = (float)NT0; gam = g00[t-32]; bet = b00[t-32]; }
        __threadfence();
        double inv  = 1.0 / (double)pN;
        double mean = d_scr.sum[off] * inv;
        double var  = d_scr.sqs[off] * inv - mean * mean;
        double sc   = (double)gam * rsqrt(var + 1e-5);
        d_p1s[t] = (float)sc;
        d_p1b[t] = (float)((double)bet - mean * sc);
    }
}

// ---------------- fused layer1-recompute + layer2 + stats + max/min --------
template<int CMID, int COUT, int NS, int P1OFF, int COLOFF>
__device__ __forceinline__ void l2big_body(
    int bid, const float* __restrict__ in, int ntot,
    const float* __restrict__ W1, const float* __restrict__ W2,
    float* __restrict__ sW1, float* __restrict__ sW2,
    float* __restrict__ sS1, float* __restrict__ sB1,
    float* __restrict__ shm, float* __restrict__ shq, int off)
{
    const int CINP = 20;
    for (int i = threadIdx.x; i < CMID * CINP; i += 256) {
        int o = i / CINP, c = i % CINP;
        sW1[i] = (c < 19) ? W1[o * 19 + c] : 0.f;
    }
    for (int i = threadIdx.x; i < COUT * CMID; i += 256)
        sW2[i] = W2[i];
    if (threadIdx.x < CMID) {
        sS1[threadIdx.x] = d_p1s[P1OFF + threadIdx.x];
        sB1[threadIdx.x] = d_p1b[P1OFF + threadIdx.x];
    }
    for (int i = threadIdx.x; i < COUT; i += 256) { shm[i] = 0.f; shq[i] = 0.f; }
    __syncthreads();

    int s    = bid * 256 + threadIdx.x;
    int lane = threadIdx.x & 31;
    int q    = s / NS;

    float x[CINP];
    #pragma unroll
    for (int c = 0; c < CINP; c++)
        x[c] = (c < 19) ? in[(size_t)c * ntot + s] : 0.f;

    // recompute layer 1 (same FMA order as l1stats), then BN+ReLU
    float y[CMID];
    const float4* sW14 = (const float4*)sW1;
    #pragma unroll
    for (int m = 0; m < CMID; m++) {
        float a = 0.f;
        #pragma unroll
        for (int c4 = 0; c4 < CINP / 4; c4++) {
            float4 wv = sW14[m * (CINP / 4) + c4];
            a = fmaf(x[c4*4+0], wv.x, a);
            a = fmaf(x[c4*4+1], wv.y, a);
            a = fmaf(x[c4*4+2], wv.z, a);
            a = fmaf(x[c4*4+3], wv.w, a);
        }
        y[m] = fmaxf(fmaf(a, sS1[m], sB1[m]), 0.f);
    }

    // layer 2: per output channel, stats + per-query max/min
    const float4* sW24 = (const float4*)sW2;
    #pragma unroll
    for (int o = 0; o < COUT; o++) {
        float a = 0.f;
        #pragma unroll
        for (int m4 = 0; m4 < CMID / 4; m4++) {
            float4 wv = sW24[o * (CMID / 4) + m4];
            a = fmaf(y[m4*4+0], wv.x, a);
            a = fmaf(y[m4*4+1], wv.y, a);
            a = fmaf(y[m4*4+2], wv.z, a);
            a = fmaf(y[m4*4+3], wv.w, a);
        }
        float sm = a, sq = a * a;
        #pragma unroll
        for (int d = 16; d; d >>= 1) {
            sm += __shfl_down_sync(0xffffffffu, sm, d);
            sq += __shfl_down_sync(0xffffffffu, sq, d);
        }
        if (lane == 0) { atomicAdd(&shm[o], sm); atomicAdd(&shq[o], sq); }

        float mx = a, mn = a;
        #pragma unroll
        for (int d = NS / 2; d; d >>= 1) {
            mx = fmaxf(mx, __shfl_xor_sync(0xffffffffu, mx, d));
            mn = fminf(mn, __shfl_xor_sync(0xffffffffu, mn, d));
        }
        if ((lane & (NS - 1)) == 0) {
            d_mx[q * 96 + COLOFF + o] = mx;
            d_mn[q * 96 + COLOFF + o] = mn;
        }
    }
    __syncthreads();
    if (threadIdx.x < COUT) {
        atomicAdd(&d_scr.sum[off + threadIdx.x], (double)shm[threadIdx.x]);
        atomicAdd(&d_scr.sqs[off + threadIdx.x], (double)shq[threadIdx.x]);
    }
}

// ---------------- kernel 4: big fused layer-2 kernel ------------------------
__global__ void __launch_bounds__(256) l2big_kernel(
    const float* __restrict__ w10, const float* __restrict__ w11,
    const float* __restrict__ w00, const float* __restrict__ w01,
    const float* __restrict__ g11, const float* __restrict__ b11,
    const float* __restrict__ g01, const float* __restrict__ b01)
{
    __shared__ __align__(16) float sW1[32 * 20];
    __shared__ __align__(16) float sW2[64 * 32];
    __shared__ float sS1[32], sB1[32], shm[64], shq[64];
    __shared__ int is_last;

    if (blockIdx.x < 512)
        l2big_body<32, 64, NS1, 0, 32>(blockIdx.x, d_g1, NT1, w10, w11,
                                       sW1, sW2, sS1, sB1, shm, shq, OFF_S1L2);
    else
        l2big_body<16, 32, NS0, 32, 0>(blockIdx.x - 512, d_g0, NT0, w00, w01,
                                       sW1, sW2, sS1, sB1, shm, shq, OFF_S0L2);

    if (threadIdx.x == 0) {
        __threadfence();
        unsigned d = atomicAdd(&d_scr.ctr2, 1u);
        is_last = (d == NB_L2 - 1);
    }
    __syncthreads();
    if (is_last && threadIdx.x < 96) {
        int t = threadIdx.x;
        int off; float pN, gam, bet;
        if (t < 32) { off = OFF_S0L2 + t; pN = (float)NT0; gam = g01[t]; bet = b01[t]; }
        else        { off = OFF_S1L2 + t - 32; pN = (float)NT1; gam = g11[t-32]; bet = b11[t-32]; }
        __threadfence();
        double inv  = 1.0 / (double)pN;
        double mean = d_scr.sum[off] * inv;
        double var  = d_scr.sqs[off] * inv - mean * mean;
        double sc   = (double)gam * rsqrt(var + 1e-5);
        d_p2s[t] = (float)sc;
        d_p2b[t] = (float)((double)bet - mean * sc);
    }
}

// ---------------- kernel 5: finalize (BN affine + ReLU on extremals) -------
__global__ void __launch_bounds__(256) finalize_kernel(int out_off,
                                                       float* __restrict__ out)
{
    int idx = blockIdx.x * 256 + threadIdx.x;
    if (idx >= NQK * 96) return;
    int col = idx % 96;
    float sc = d_p2s[col], bi = d_p2b[col];
    float v = (sc >= 0.f) ? d_mx[idx] : d_mn[idx];
    out[out_off + idx] = fmaxf(fmaf(v, sc, bi), 0.f);
}

// ---------------- launch ----------------------------------------------------
extern "C" void kernel_launch(void* const* d_in, const int* in_sizes, int n_in,
                              void* d_out, int out_size)
{
    const float* xyz  = (const float*)d_in[0];
    const float* nxyz = (const float*)d_in[2];
    const float* feat = (const float*)d_in[4];
    const float* w00 = (const float*)d_in[5];
    const float* g00 = (const float*)d_in[6];
    const float* b00 = (const float*)d_in[7];
    const float* w01 = (const float*)d_in[8];
    const float* g01 = (const float*)d_in[9];
    const float* b01 = (const float*)d_in[10];
    const float* w10 = (const float*)d_in[11];
    const float* g10 = (const float*)d_in[12];
    const float* b10 = (const float*)d_in[13];
    const float* w11 = (const float*)d_in[14];
    const float* g11 = (const float*)d_in[15];
    const float* b11 = (const float*)d_in[16];
    float* out = (float*)d_out;

    void* scr;
    cudaGetSymbolAddress(&scr, d_scr);

    int out_off = out_size - NQK * 96;
    if (out_off < 0) out_off = 0;

    cudaMemsetAsync(scr, 0, sizeof(Scratch));                       // 1

    prep_count_kernel<<<(2 * N_PERK + 255) / 256, 256>>>(xyz);      // 2
    scatter_kernel<<<(2 * N_PERK + 255) / 256, 256>>>();            // 3
    bq_block_kernel<<<NQK, 128>>>(nxyz, feat);                      // 4
    l1stats_kernel<<<NB_L1, 256>>>(w10, w00, g10, b10, g00, b00);   // 5
    l2big_kernel<<<NB_L2, 256>>>(w10, w11, w00, w01,                // 6 <- capture
                                 g11, b11, g01, b01);
    finalize_kernel<<<(NQK * 96 + 255) / 256, 256>>>(out_off, out); // 7

    if (out_off > 0)
        cudaMemcpyAsync(out, nxyz, (size_t)out_off * sizeof(float),
                        cudaMemcpyDeviceToDevice);                  // 8
}

// round 9
// speedup vs baseline: 1.0106x; 1.0106x over previous
#include <cuda_runtime.h>
#include <limits.h>

// Problem constants (fixed by setup_inputs)
#define N_PERK 16384
#define NQK    4096      // B * M_PER
#define CINF   16
#define NS0    16
#define NS1    32
#define NT0    65536     // NQK * NS0
#define NT1    131072    // NQK * NS1

// channel offsets into the 144-wide BN stat arrays
#define OFF_S0L1 0
#define OFF_S0L2 16
#define OFF_S1L1 48
#define OFF_S1L2 80

#define GRIDR  10
#define NCELLS 1000
#define CAP1   768
#define CAP0   192

// ---------------- scratch (device globals; no allocation allowed) ----------
struct Scratch {
    int    cellcnt[2016];
    int    cellofs[2016];
    double sum[144];
    double sqs[144];
};
__device__ Scratch d_scr;
__device__ int    d_cellstart[2048];
__device__ float4 d_pts4 [2 * N_PERK]; // original order: (x,y,z,|p|^2)
__device__ float4 d_cpts4[2 * N_PERK]; // cell-sorted:    (x,y,z,idx_bits)
__device__ float  d_g0 [19 * NT0];
__device__ float  d_g1 [19 * NT1];
__device__ float  d_xa0[16 * NT0];
__device__ float  d_xb0[32 * NT0];
__device__ float  d_xa1[32 * NT1];
__device__ float  d_xb1[64 * NT1];

// ---------------- kernel 0: pack points + count cells -----------------------
__global__ void prep_count_kernel(const float* __restrict__ xyz)
{
    int i = blockIdx.x * blockDim.x + threadIdx.x;
    if (i >= 2 * N_PERK) return;
    float x = xyz[i*3+0], y = xyz[i*3+1], z = xyz[i*3+2];
    d_pts4[i] = make_float4(x, y, z, fmaf(z, z, fmaf(y, y, x*x)));
    int cx = min(GRIDR-1, max(0, (int)(x * 10.f)));
    int cy = min(GRIDR-1, max(0, (int)(y * 10.f)));
    int cz = min(GRIDR-1, max(0, (int)(z * 10.f)));
    int cell = (i >> 14) * NCELLS + (cz * GRIDR + cy) * GRIDR + cx;
    atomicAdd(&d_scr.cellcnt[cell], 1);
}

// ---------------- kernel 1: fused scan + scatter ----------------------------
__global__ void __launch_bounds__(256) scatter_kernel()
{
    __shared__ int sstart[2048];
    __shared__ int warpsum[8], warpbase[8];
    int t = threadIdx.x;
    int lane = t & 31, w = t >> 5;

    int v[8];
    int loc = 0;
    int base = t * 8;
    #pragma unroll
    for (int j = 0; j < 8; j++) {
        int k = base + j;
        int c = (k < 2 * NCELLS) ? d_scr.cellcnt[k] : 0;
        v[j] = loc;
        loc += c;
    }
    int inc = loc;
    #pragma unroll
    for (int d = 1; d < 32; d <<= 1) {
        int x = __shfl_up_sync(0xffffffffu, inc, d);
        if (lane >= d) inc += x;
    }
    if (lane == 31) warpsum[w] = inc;
    __syncthreads();
    if (t == 0) {
        int s = 0;
        #pragma unroll
        for (int i = 0; i < 8; i++) { warpbase[i] = s; s += warpsum[i]; }
    }
    __syncthreads();
    int tbase = warpbase[w] + (inc - loc);
    #pragma unroll
    for (int j = 0; j < 8; j++)
        sstart[base + j] = tbase + v[j];
    __syncthreads();

    if (blockIdx.x == 0)
        for (int k = t; k <= 2 * NCELLS; k += 256)
            d_cellstart[k] = (k < 2048) ? sstart[k] : 0;

    int i = blockIdx.x * 256 + t;
    if (i < 2 * N_PERK) {
        float4 p = d_pts4[i];
        int cx = min(GRIDR-1, max(0, (int)(p.x * 10.f)));
        int cy = min(GRIDR-1, max(0, (int)(p.y * 10.f)));
        int cz = min(GRIDR-1, max(0, (int)(p.z * 10.f)));
        int cell = (i >> 14) * NCELLS + (cz * GRIDR + cy) * GRIDR + cx;
        int pos = sstart[cell] + atomicAdd(&d_scr.cellofs[cell], 1);
        d_cpts4[pos] = make_float4(p.x, p.y, p.z,
                                   __int_as_float(i & (N_PERK - 1)));
    }
}

// ---------------- select k smallest indices from cand[cnt] -----------------
__device__ __forceinline__ int select_k(const int* __restrict__ cand, int cnt,
                                        const int* __restrict__ bc,
                                        int* __restrict__ sel2,
                                        int* __restrict__ fin,
                                        int k, int lane, unsigned low)
{
    if (cnt <= k) {
        for (int i = lane; i < cnt; i += 32) fin[i] = cand[i];
        return cnt;
    }
    int p = bc[lane];
    #pragma unroll
    for (int d = 1; d < 32; d <<= 1) {
        int t = __shfl_up_sync(0xffffffffu, p, d);
        if (lane >= d) p += t;
    }
    unsigned mk = __ballot_sync(0xffffffffu, p >= k);
    int bstar = __ffs(mk) - 1;
    int base  = (bstar > 0) ? __shfl_sync(0xffffffffu, p, bstar - 1) : 0;
    int need  = k - base;
    int B0 = bstar << 9, B1 = (bstar + 1) << 9;

    int n_auto = 0, n_mid = 0;
    for (int i0 = 0; i0 < cnt; i0 += 32) {
        int i = i0 + lane;
        int v = (i < cnt) ? cand[i] : INT_MAX;
        bool a = (v < B0);
        bool m = (v >= B0) && (v < B1);
        unsigned ma = __ballot_sync(0xffffffffu, a);
        unsigned mm = __ballot_sync(0xffffffffu, m);
        if (a) fin[n_auto + __popc(ma & low)] = v;
        else if (m) {
            int pos = n_mid + __popc(mm & low);
            if (pos < 64) sel2[pos] = v;
        }
        n_auto += __popc(ma);
        n_mid  += __popc(mm);
    }
    if (n_mid > 64) n_mid = 64;
    __syncwarp();

    int last = -1;
    for (int j = 0; j < need; j++) {
        int v = INT_MAX;
        for (int i = lane; i < n_mid; i += 32) {
            int x = sel2[i];
            if (x > last && x < v) v = x;
        }
        #pragma unroll
        for (int d = 16; d; d >>= 1)
            v = min(v, __shfl_xor_sync(0xffffffffu, v, d));
        fin[base + j] = v;
        last = v;
    }
    return k;
}

// ---------------- kernel 2: block-per-query dual-scale ball query ----------
// 64 points per warp-iteration; idx packed in cpts4.w; |p|^2 recomputed with
// the same fma expression prep used (bit-identical d2).
__global__ void __launch_bounds__(128) bq_block_kernel(
    const float* __restrict__ nxyz, const float* __restrict__ feat)
{
    __shared__ int cand1[CAP1], cand0[CAP0];
    __shared__ int bc1[32], bc0[32];
    __shared__ int sel2a[64], sel2b[64];
    __shared__ int fin1[NS1], fin0[NS0];
    __shared__ int scnt1, scnt0, slmin1, slmin0, m1n_s, m0n_s;

    int tid  = threadIdx.x;
    int wid  = tid >> 5;
    int lane = tid & 31;
    unsigned low = (1u << lane) - 1u;

    int q = blockIdx.x;
    int b = q >> 11;
    int nbase = b << 14;

    if (tid < 32) { bc1[tid] = 0; bc0[tid] = 0; }
    if (tid == 0) {
        scnt1 = 0; scnt0 = 0;
        slmin1 = INT_MAX; slmin0 = INT_MAX;
    }
    __syncthreads();

    float qx = nxyz[q*3+0], qy = nxyz[q*3+1], qz = nxyz[q*3+2];
    float q2 = fmaf(qz, qz, fmaf(qy, qy, qx*qx));

    int cy = min(GRIDR-1, max(0, (int)(qy * 10.f)));
    int cz = min(GRIDR-1, max(0, (int)(qz * 10.f)));
    int zlo = max(0, cz-2), zhi = min(GRIDR-1, cz+2);
    int ylo = max(0, cy-2), yhi = min(GRIDR-1, cy+2);
    int nz = zhi - zlo + 1, ny = yhi - ylo + 1;

    const float RP2 = 0.04f + 1e-4f;
    int lmin1 = INT_MAX, lmin0 = INT_MAX;

    for (int ri = wid; ri < nz * ny; ri += 4) {
        int zz = zlo + ri / ny;
        int yy = ylo + ri % ny;
        float dz = fmaxf(0.f, fmaxf(zz * 0.1f - qz, qz - (zz+1) * 0.1f));
        float dy = fmaxf(0.f, fmaxf(yy * 0.1f - qy, qy - (yy+1) * 0.1f));
        float r2 = fmaf(dy, dy, dz * dz);
        if (r2 >= RP2) continue;
        float dxm = sqrtf(RP2 - r2);
        int xlo = max(0, (int)floorf((qx - dxm) * 10.f));
        int xhi = min(GRIDR-1, (int)floorf((qx + dxm) * 10.f));
        if (xlo > xhi) continue;
        int row = b * NCELLS + (zz * GRIDR + yy) * GRIDR;
        int s = d_cellstart[row + xlo];
        int e = d_cellstart[row + xhi + 1];
        for (int i0 = s; i0 < e; i0 += 64) {
            int ia = i0 + lane;
            int ib = ia + 32;
            bool oka1 = false, oka0 = false, okb1 = false, okb0 = false;
            int idxa = 0, idxb = 0;
            if (ia < e) {
                float4 p = d_cpts4[ia];
                idxa = __float_as_int(p.w);
                float p2 = fmaf(p.z, p.z, fmaf(p.y, p.y, p.x*p.x));
                float dt = fmaf(qz, p.z, fmaf(qy, p.y, qx*p.x));
                float d2 = fmaf(-2.f, dt, q2 + p2);
                oka1 = d2 < 0.04f;
                oka0 = d2 < 0.01f;
            }
            if (ib < e) {
                float4 p = d_cpts4[ib];
                idxb = __float_as_int(p.w);
                float p2 = fmaf(p.z, p.z, fmaf(p.y, p.y, p.x*p.x));
                float dt = fmaf(qz, p.z, fmaf(qy, p.y, qx*p.x));
                float d2 = fmaf(-2.f, dt, q2 + p2);
                okb1 = d2 < 0.04f;
                okb0 = d2 < 0.01f;
            }
            unsigned m1a = __ballot_sync(0xffffffffu, oka1);
            unsigned m1b = __ballot_sync(0xffffffffu, okb1);
            unsigned m0a = __ballot_sync(0xffffffffu, oka0);
            unsigned m0b = __ballot_sync(0xffffffffu, okb0);
            int c1a = __popc(m1a), tot1 = c1a + __popc(m1b);
            int c0a = __popc(m0a), tot0 = c0a + __popc(m0b);
            if (tot1) {
                int bpos = 0;
                if (lane == 0) bpos = atomicAdd(&scnt1, tot1);
                bpos = __shfl_sync(0xffffffffu, bpos, 0);
                if (oka1) {
                    lmin1 = min(lmin1, idxa);
                    int pos = bpos + __popc(m1a & low);
                    if (pos < CAP1) { cand1[pos] = idxa; atomicAdd(&bc1[idxa >> 9], 1); }
                }
                if (okb1) {
                    lmin1 = min(lmin1, idxb);
                    int pos = bpos + c1a + __popc(m1b & low);
                    if (pos < CAP1) { cand1[pos] = idxb; atomicAdd(&bc1[idxb >> 9], 1); }
                }
            }
            if (tot0) {
                int bpos = 0;
                if (lane == 0) bpos = atomicAdd(&scnt0, tot0);
                bpos = __shfl_sync(0xffffffffu, bpos, 0);
                if (oka0) {
                    lmin0 = min(lmin0, idxa);
                    int pos = bpos + __popc(m0a & low);
                    if (pos < CAP0) { cand0[pos] = idxa; atomicAdd(&bc0[idxa >> 9], 1); }
                }
                if (okb0) {
                    lmin0 = min(lmin0, idxb);
                    int pos = bpos + c0a + __popc(m0b & low);
                    if (pos < CAP0) { cand0[pos] = idxb; atomicAdd(&bc0[idxb >> 9], 1); }
                }
            }
        }
    }
    #pragma unroll
    for (int d = 16; d; d >>= 1) {
        lmin1 = min(lmin1, __shfl_xor_sync(0xffffffffu, lmin1, d));
        lmin0 = min(lmin0, __shfl_xor_sync(0xffffffffu, lmin0, d));
    }
    if (lane == 0) {
        atomicMin(&slmin1, lmin1);
        atomicMin(&slmin0, lmin0);
    }
    __syncthreads();

    if (wid == 0) {
        int n = select_k(cand1, min(scnt1, CAP1), bc1, sel2a, fin1, NS1, lane, low);
        if (lane == 0) m1n_s = n;
    } else if (wid == 1) {
        int n = select_k(cand0, min(scnt0, CAP0), bc0, sel2b, fin0, NS0, lane, low);
        if (lane == 0) m0n_s = n;
    }
    __syncthreads();

    if (wid == 0) {   // scale-1 grouping
        int m1n = m1n_s;
        int sidx = q * NS1 + lane;
        float g[19];
        if (m1n == 0) {
            #pragma unroll
            for (int c = 0; c < 19; c++) g[c] = 0.f;
        } else {
            int id = (lane < m1n) ? fin1[lane] : slmin1;
            float4 p = d_pts4[nbase + id];
            g[0] = p.x - qx; g[1] = p.y - qy; g[2] = p.z - qz;
            const float4* f = (const float4*)(feat + (size_t)(nbase + id) * CINF);
            float4 f0 = f[0], f1 = f[1], f2 = f[2], f3 = f[3];
            g[3]=f0.x; g[4]=f0.y; g[5]=f0.z; g[6]=f0.w;
            g[7]=f1.x; g[8]=f1.y; g[9]=f1.z; g[10]=f1.w;
            g[11]=f2.x; g[12]=f2.y; g[13]=f2.z; g[14]=f2.w;
            g[15]=f3.x; g[16]=f3.y; g[17]=f3.z; g[18]=f3.w;
        }
        #pragma unroll
        for (int c = 0; c < 19; c++) d_g1[c * NT1 + sidx] = g[c];
    } else if (wid == 1 && lane < NS0) {   // scale-0 grouping
        int m0n = m0n_s;
        int sidx = q * NS0 + lane;
        float g[19];
        if (m0n == 0) {
            #pragma unroll
            for (int c = 0; c < 19; c++) g[c] = 0.f;
        } else {
            int id = (lane < m0n) ? fin0[lane] : slmin0;
            float4 p = d_pts4[nbase + id];
            g[0] = p.x - qx; g[1] = p.y - qy; g[2] = p.z - qz;
            const float4* f = (const float4*)(feat + (size_t)(nbase + id) * CINF);
            float4 f0 = f[0], f1 = f[1], f2 = f[2], f3 = f[3];
            g[3]=f0.x; g[4]=f0.y; g[5]=f0.z; g[6]=f0.w;
            g[7]=f1.x; g[8]=f1.y; g[9]=f1.z; g[10]=f1.w;
            g[11]=f2.x; g[12]=f2.y; g[13]=f2.z; g[14]=f2.w;
            g[15]=f3.x; g[16]=f3.y; g[17]=f3.z; g[18]=f3.w;
        }
        #pragma unroll
        for (int c = 0; c < 19; c++) d_g0[c * NT0 + sidx] = g[c];
    }
}

// ---------------- GEMV body (templated SPT, 256-thread blocks) -------------
template<int CIN, int CINP, int COUT, bool AFF, int SPT>
__device__ __forceinline__ void gemv_body(
    int bid, const float* __restrict__ in, int ntot,
    const float* __restrict__ W,
    const float* __restrict__ gamma_, const float* __restrict__ beta_,
    float pN, int poff, float* __restrict__ out, int off,
    float* __restrict__ sW, float* __restrict__ sS, float* __restrict__ sB,
    float* __restrict__ shm, float* __restrict__ shq)
{
    for (int i = threadIdx.x; i < COUT * CINP; i += 256) {
        int o = i / CINP, c = i % CINP;
        sW[i] = (c < CIN) ? W[o * CIN + c] : 0.f;
    }
    for (int i = threadIdx.x; i < COUT; i += 256) { shm[i] = 0.f; shq[i] = 0.f; }
    if (AFF) {
        for (int i = threadIdx.x; i < CIN; i += 256) {
            double inv  = 1.0 / (double)pN;
            double mean = d_scr.sum[poff + i] * inv;
            double var  = d_scr.sqs[poff + i] * inv - mean * mean;
            double sc   = (double)gamma_[i] * rsqrt(var + 1e-5);
            sS[i] = (float)sc;
            sB[i] = (float)((double)beta_[i] - mean * sc);
        }
    }
    __syncthreads();

    int s    = (bid * 256 + threadIdx.x) * SPT;
    int lane = threadIdx.x & 31;

    float x[CINP][SPT];
    #pragma unroll
    for (int c = 0; c < CINP; c++) {
        if (c < CIN) {
            const float* p = in + (size_t)c * ntot + s;
            if (SPT == 4) {
                float4 v = *(const float4*)p;
                x[c][0] = v.x; x[c][1] = v.y; x[c][2] = v.z; x[c][3] = v.w;
            } else {
                float2 v = *(const float2*)p;
                x[c][0] = v.x; x[c][1] = v.y;
            }
            if (AFF) {
                #pragma unroll
                for (int k = 0; k < SPT; k++)
                    x[c][k] = fmaxf(fmaf(x[c][k], sS[c], sB[c]), 0.f);
            }
        } else {
            #pragma unroll
            for (int k = 0; k < SPT; k++) x[c][k] = 0.f;
        }
    }

    const float4* sW4 = (const float4*)sW;
    #pragma unroll
    for (int o = 0; o < COUT; o++) {
        float acc[SPT];
        #pragma unroll
        for (int k = 0; k < SPT; k++) acc[k] = 0.f;
        #pragma unroll
        for (int c4 = 0; c4 < CINP / 4; c4++) {
            float4 wv = sW4[o * (CINP / 4) + c4];
            #pragma unroll
            for (int k = 0; k < SPT; k++) {
                acc[k] = fmaf(x[c4*4+0][k], wv.x, acc[k]);
                acc[k] = fmaf(x[c4*4+1][k], wv.y, acc[k]);
                acc[k] = fmaf(x[c4*4+2][k], wv.z, acc[k]);
                acc[k] = fmaf(x[c4*4+3][k], wv.w, acc[k]);
            }
        }
        float* po = out + (size_t)o * ntot + s;
        if (SPT == 4) *(float4*)po = make_float4(acc[0], acc[1], acc[2], acc[3]);
        else          *(float2*)po = make_float2(acc[0], acc[1]);

        float sm = 0.f, sq = 0.f;
        #pragma unroll
        for (int k = 0; k < SPT; k++) { sm += acc[k]; sq = fmaf(acc[k], acc[k], sq); }
        #pragma unroll
        for (int d = 16; d; d >>= 1) {
            sm += __shfl_down_sync(0xffffffffu, sm, d);
            sq += __shfl_down_sync(0xffffffffu, sq, d);
        }
        if (lane == 0) { atomicAdd(&shm[o], sm); atomicAdd(&shq[o], sq); }
    }
    __syncthreads();
    if (threadIdx.x < COUT) {
        atomicAdd(&d_scr.sum[off + threadIdx.x], (double)shm[threadIdx.x]);
        atomicAdd(&d_scr.sqs[off + threadIdx.x], (double)shq[threadIdx.x]);
    }
}

// ---------------- kernel 3: fused layer-1 GEMVs (SPT=4) --------------------
// blocks [0,128): scale1 (NT1/1024). blocks [128,192): scale0 (NT0/1024)
__global__ void __launch_bounds__(256) gemv_l1_kernel(
    const float* __restrict__ w10, const float* __restrict__ w00)
{
    __shared__ __align__(16) float sW[32 * 20];
    __shared__ float sS[32], sB[32], shm[32], shq[32];
    if (blockIdx.x < 128)
        gemv_body<19, 20, 32, false, 4>(blockIdx.x, d_g1, NT1, w10,
                                        nullptr, nullptr, 0.f, 0,
                                        d_xa1, OFF_S1L1, sW, sS, sB, shm, shq);
    else
        gemv_body<19, 20, 16, false, 4>(blockIdx.x - 128, d_g0, NT0, w00,
                                        nullptr, nullptr, 0.f, 0,
                                        d_xa0, OFF_S0L1, sW, sS, sB, shm, shq);
}

// ---------------- kernel 4: fused layer-2 GEMVs ----------------------------
// blocks [0,256): scale1 SPT=2 (NT1/512). blocks [256,320): scale0 SPT=4.
__global__ void __launch_bounds__(256) gemv_l2_kernel(
    const float* __restrict__ w11, const float* __restrict__ g10,
    const float* __restrict__ b10,
    const float* __restrict__ w01, const float* __restrict__ g00,
    const float* __restrict__ b00)
{
    __shared__ __align__(16) float sW[64 * 32];
    __shared__ float sS[32], sB[32], shm[64], shq[64];
    if (blockIdx.x < 256)
        gemv_body<32, 32, 64, true, 2>(blockIdx.x, d_xa1, NT1, w11, g10, b10,
                                       (float)NT1, OFF_S1L1,
                                       d_xb1, OFF_S1L2, sW, sS, sB, shm, shq);
    else
        gemv_body<16, 16, 32, true, 4>(blockIdx.x - 256, d_xa0, NT0, w01, g00, b00,
                                       (float)NT0, OFF_S0L1,
                                       d_xb0, OFF_S0L2, sW, sS, sB, shm, shq);
}

// ---------------- pool body -------------------------------------------------
template<int NS, int COUT>
__device__ __forceinline__ void pool_body(
    int bid, const float* __restrict__ x, int ntot, int off, float pN,
    const float* __restrict__ gamma_, const float* __restrict__ beta_,
    int col_off, int out_off, float* __restrict__ out,
    float* __restrict__ psc, float* __restrict__ pbi)
{
    if (threadIdx.x < COUT) {
        int i = threadIdx.x;
        double inv  = 1.0 / (double)pN;
        double mean = d_scr.sum[off + i] * inv;
        double var  = d_scr.sqs[off + i] * inv - mean * mean;
        double sc   = (double)gamma_[i] * rsqrt(var + 1e-5);
        psc[i] = (float)sc;
        pbi[i] = (float)((double)beta_[i] - mean * sc);
    }
    __syncthreads();

    int warp = (bid * 256 + threadIdx.x) >> 5;
    int lane = threadIdx.x & 31;
    int q = warp * (32 / NS) + lane / NS;
    int j = lane % NS;
    if (q >= NQK) return;
    #pragma unroll 4
    for (int o = 0; o < COUT; o++) {
        float v = fmaf(x[(size_t)o * ntot + q * NS + j], psc[o], pbi[o]);
        #pragma unroll
        for (int d = NS / 2; d; d >>= 1)
            v = fmaxf(v, __shfl_xor_sync(0xffffffffu, v, d));
        if (j == 0) out[out_off + q * 96 + col_off + o] = fmaxf(v, 0.f);
    }
}

// ---------------- kernel 5: fused pools ------------------------------------
__global__ void __launch_bounds__(256) pool_kernel(
    const float* __restrict__ g11, const float* __restrict__ b11,
    const float* __restrict__ g01, const float* __restrict__ b01,
    int out_off, float* __restrict__ out)
{
    __shared__ float psc[64], pbi[64];
    if (blockIdx.x < 512)
        pool_body<NS1, 64>(blockIdx.x, d_xb1, NT1, OFF_S1L2, (float)NT1,
                           g11, b11, 32, out_off, out, psc, pbi);
    else
        pool_body<NS0, 32>(blockIdx.x - 512, d_xb0, NT0, OFF_S0L2, (float)NT0,
                           g01, b01, 0, out_off, out, psc, pbi);
}

// ---------------- launch ----------------------------------------------------
extern "C" void kernel_launch(void* const* d_in, const int* in_sizes, int n_in,
                              void* d_out, int out_size)
{
    const float* xyz  = (const float*)d_in[0];
    const float* nxyz = (const float*)d_in[2];
    const float* feat = (const float*)d_in[4];
    const float* w00 = (const float*)d_in[5];
    const float* g00 = (const float*)d_in[6];
    const float* b00 = (const float*)d_in[7];
    const float* w01 = (const float*)d_in[8];
    const float* g01 = (const float*)d_in[9];
    const float* b01 = (const float*)d_in[10];
    const float* w10 = (const float*)d_in[11];
    const float* g10 = (const float*)d_in[12];
    const float* b10 = (const float*)d_in[13];
    const float* w11 = (const float*)d_in[14];
    const float* g11 = (const float*)d_in[15];
    const float* b11 = (const float*)d_in[16];
    float* out = (float*)d_out;

    void* scr;
    cudaGetSymbolAddress(&scr, d_scr);

    int out_off = out_size - NQK * 96;
    if (out_off < 0) out_off = 0;
    if (out_off > 0)
        cudaMemcpyAsync(out, nxyz, (size_t)out_off * sizeof(float),
                        cudaMemcpyDeviceToDevice);

    cudaMemsetAsync(scr, 0, sizeof(Scratch));                       // 1

    prep_count_kernel<<<(2 * N_PERK + 255) / 256, 256>>>(xyz);      // 2
    scatter_kernel<<<(2 * N_PERK + 255) / 256, 256>>>();            // 3
    bq_block_kernel<<<NQK, 128>>>(nxyz, feat);                      // 4
    gemv_l1_kernel<<<192, 256>>>(w10, w00);                         // 5
    gemv_l2_kernel<<<320, 256>>>(w11, g10, b10, w01, g00, b00);     // 6 <- capture
    pool_kernel<<<768, 256>>>(g11, b11, g01, b01, out_off, out);    // 7
}

// round 10
// speedup vs baseline: 1.2723x; 1.2589x over previous
#include <cuda_runtime.h>
#include <limits.h>

// Problem constants (fixed by setup_inputs)
#define N_PERK 16384
#define NQK    4096      // B * M_PER
#define CINF   16
#define NS0    16
#define NS1    32
#define NT0    65536     // NQK * NS0
#define NT1    131072    // NQK * NS1

// channel offsets into the 144-wide BN stat arrays
#define OFF_S0L1 0
#define OFF_S0L2 16
#define OFF_S1L1 48
#define OFF_S1L2 80

#define GRIDR  10
#define NCELLS 1000
#define CAP1   768
#define CAP0   192
#define NB_L2  384

// ---------------- scratch (device globals; no allocation allowed) ----------
struct Scratch {
    int      cellcnt[2016];
    int      cellofs[2016];
    double   sum[144];
    double   sqs[144];
    unsigned ctr2;
};
__device__ Scratch d_scr;
__device__ int    d_cellstart[2048];
__device__ float4 d_pts4 [2 * N_PERK]; // original order: (x,y,z,|p|^2)
__device__ float4 d_cpts4[2 * N_PERK]; // cell-sorted:    (x,y,z,idx_bits)
__device__ float  d_g0 [19 * NT0];
__device__ float  d_g1 [19 * NT1];
__device__ float  d_xa0[16 * NT0];
__device__ float  d_xa1[32 * NT1];
__device__ float  d_mx [NQK * 96];     // per-(query,col) max of pre-BN layer-2
__device__ float  d_mn [NQK * 96];     // per-(query,col) min
__device__ float  d_p2s[96], d_p2b[96];

// ---------------- kernel 0: pack points + count cells -----------------------
__global__ void prep_count_kernel(const float* __restrict__ xyz)
{
    int i = blockIdx.x * blockDim.x + threadIdx.x;
    if (i >= 2 * N_PERK) return;
    float x = xyz[i*3+0], y = xyz[i*3+1], z = xyz[i*3+2];
    d_pts4[i] = make_float4(x, y, z, fmaf(z, z, fmaf(y, y, x*x)));
    int cx = min(GRIDR-1, max(0, (int)(x * 10.f)));
    int cy = min(GRIDR-1, max(0, (int)(y * 10.f)));
    int cz = min(GRIDR-1, max(0, (int)(z * 10.f)));
    int cell = (i >> 14) * NCELLS + (cz * GRIDR + cy) * GRIDR + cx;
    atomicAdd(&d_scr.cellcnt[cell], 1);
}

// ---------------- kernel 1: fused scan + scatter ----------------------------
__global__ void __launch_bounds__(256) scatter_kernel()
{
    __shared__ int sstart[2048];
    __shared__ int warpsum[8], warpbase[8];
    int t = threadIdx.x;
    int lane = t & 31, w = t >> 5;

    int v[8];
    int loc = 0;
    int base = t * 8;
    #pragma unroll
    for (int j = 0; j < 8; j++) {
        int k = base + j;
        int c = (k < 2 * NCELLS) ? d_scr.cellcnt[k] : 0;
        v[j] = loc;
        loc += c;
    }
    int inc = loc;
    #pragma unroll
    for (int d = 1; d < 32; d <<= 1) {
        int x = __shfl_up_sync(0xffffffffu, inc, d);
        if (lane >= d) inc += x;
    }
    if (lane == 31) warpsum[w] = inc;
    __syncthreads();
    if (t == 0) {
        int s = 0;
        #pragma unroll
        for (int i = 0; i < 8; i++) { warpbase[i] = s; s += warpsum[i]; }
    }
    __syncthreads();
    int tbase = warpbase[w] + (inc - loc);
    #pragma unroll
    for (int j = 0; j < 8; j++)
        sstart[base + j] = tbase + v[j];
    __syncthreads();

    if (blockIdx.x == 0)
        for (int k = t; k <= 2 * NCELLS; k += 256)
            d_cellstart[k] = (k < 2048) ? sstart[k] : 0;

    int i = blockIdx.x * 256 + t;
    if (i < 2 * N_PERK) {
        float4 p = d_pts4[i];
        int cx = min(GRIDR-1, max(0, (int)(p.x * 10.f)));
        int cy = min(GRIDR-1, max(0, (int)(p.y * 10.f)));
        int cz = min(GRIDR-1, max(0, (int)(p.z * 10.f)));
        int cell = (i >> 14) * NCELLS + (cz * GRIDR + cy) * GRIDR + cx;
        int pos = sstart[cell] + atomicAdd(&d_scr.cellofs[cell], 1);
        d_cpts4[pos] = make_float4(p.x, p.y, p.z,
                                   __int_as_float(i & (N_PERK - 1)));
    }
}

// ---------------- select k smallest indices from cand[cnt] -----------------
__device__ __forceinline__ int select_k(const int* __restrict__ cand, int cnt,
                                        const int* __restrict__ bc,
                                        int* __restrict__ sel2,
                                        int* __restrict__ fin,
                                        int k, int lane, unsigned low)
{
    if (cnt <= k) {
        for (int i = lane; i < cnt; i += 32) fin[i] = cand[i];
        return cnt;
    }
    int p = bc[lane];
    #pragma unroll
    for (int d = 1; d < 32; d <<= 1) {
        int t = __shfl_up_sync(0xffffffffu, p, d);
        if (lane >= d) p += t;
    }
    unsigned mk = __ballot_sync(0xffffffffu, p >= k);
    int bstar = __ffs(mk) - 1;
    int base  = (bstar > 0) ? __shfl_sync(0xffffffffu, p, bstar - 1) : 0;
    int need  = k - base;
    int B0 = bstar << 9, B1 = (bstar + 1) << 9;

    int n_auto = 0, n_mid = 0;
    for (int i0 = 0; i0 < cnt; i0 += 32) {
        int i = i0 + lane;
        int v = (i < cnt) ? cand[i] : INT_MAX;
        bool a = (v < B0);
        bool m = (v >= B0) && (v < B1);
        unsigned ma = __ballot_sync(0xffffffffu, a);
        unsigned mm = __ballot_sync(0xffffffffu, m);
        if (a) fin[n_auto + __popc(ma & low)] = v;
        else if (m) {
            int pos = n_mid + __popc(mm & low);
            if (pos < 64) sel2[pos] = v;
        }
        n_auto += __popc(ma);
        n_mid  += __popc(mm);
    }
    if (n_mid > 64) n_mid = 64;
    __syncwarp();

    int last = -1;
    for (int j = 0; j < need; j++) {
        int v = INT_MAX;
        for (int i = lane; i < n_mid; i += 32) {
            int x = sel2[i];
            if (x > last && x < v) v = x;
        }
        #pragma unroll
        for (int d = 16; d; d >>= 1)
            v = min(v, __shfl_xor_sync(0xffffffffu, v, d));
        fin[base + j] = v;
        last = v;
    }
    return k;
}

// ---------------- kernel 2: block-per-query dual-scale ball query ----------
__global__ void __launch_bounds__(128) bq_block_kernel(
    const float* __restrict__ nxyz, const float* __restrict__ feat)
{
    __shared__ int cand1[CAP1], cand0[CAP0];
    __shared__ int bc1[32], bc0[32];
    __shared__ int sel2a[64], sel2b[64];
    __shared__ int fin1[NS1], fin0[NS0];
    __shared__ int scnt1, scnt0, slmin1, slmin0, m1n_s, m0n_s;

    int tid  = threadIdx.x;
    int wid  = tid >> 5;
    int lane = tid & 31;
    unsigned low = (1u << lane) - 1u;

    int q = blockIdx.x;
    int b = q >> 11;
    int nbase = b << 14;

    if (tid < 32) { bc1[tid] = 0; bc0[tid] = 0; }
    if (tid == 0) {
        scnt1 = 0; scnt0 = 0;
        slmin1 = INT_MAX; slmin0 = INT_MAX;
    }
    __syncthreads();

    float qx = nxyz[q*3+0], qy = nxyz[q*3+1], qz = nxyz[q*3+2];
    float q2 = fmaf(qz, qz, fmaf(qy, qy, qx*qx));

    int cy = min(GRIDR-1, max(0, (int)(qy * 10.f)));
    int cz = min(GRIDR-1, max(0, (int)(qz * 10.f)));
    int zlo = max(0, cz-2), zhi = min(GRIDR-1, cz+2);
    int ylo = max(0, cy-2), yhi = min(GRIDR-1, cy+2);
    int nz = zhi - zlo + 1, ny = yhi - ylo + 1;

    const float RP2 = 0.04f + 1e-4f;
    int lmin1 = INT_MAX, lmin0 = INT_MAX;

    for (int ri = wid; ri < nz * ny; ri += 4) {
        int zz = zlo + ri / ny;
        int yy = ylo + ri % ny;
        float dz = fmaxf(0.f, fmaxf(zz * 0.1f - qz, qz - (zz+1) * 0.1f));
        float dy = fmaxf(0.f, fmaxf(yy * 0.1f - qy, qy - (yy+1) * 0.1f));
        float r2 = fmaf(dy, dy, dz * dz);
        if (r2 >= RP2) continue;
        float dxm = sqrtf(RP2 - r2);
        int xlo = max(0, (int)floorf((qx - dxm) * 10.f));
        int xhi = min(GRIDR-1, (int)floorf((qx + dxm) * 10.f));
        if (xlo > xhi) continue;
        int row = b * NCELLS + (zz * GRIDR + yy) * GRIDR;
        int s = d_cellstart[row + xlo];
        int e = d_cellstart[row + xhi + 1];
        for (int i0 = s; i0 < e; i0 += 64) {
            int ia = i0 + lane;
            int ib = ia + 32;
            bool oka1 = false, oka0 = false, okb1 = false, okb0 = false;
            int idxa = 0, idxb = 0;
            if (ia < e) {
                float4 p = d_cpts4[ia];
                idxa = __float_as_int(p.w);
                float p2 = fmaf(p.z, p.z, fmaf(p.y, p.y, p.x*p.x));
                float dt = fmaf(qz, p.z, fmaf(qy, p.y, qx*p.x));
                float d2 = fmaf(-2.f, dt, q2 + p2);
                oka1 = d2 < 0.04f;
                oka0 = d2 < 0.01f;
            }
            if (ib < e) {
                float4 p = d_cpts4[ib];
                idxb = __float_as_int(p.w);
                float p2 = fmaf(p.z, p.z, fmaf(p.y, p.y, p.x*p.x));
                float dt = fmaf(qz, p.z, fmaf(qy, p.y, qx*p.x));
                float d2 = fmaf(-2.f, dt, q2 + p2);
                okb1 = d2 < 0.04f;
                okb0 = d2 < 0.01f;
            }
            unsigned m1a = __ballot_sync(0xffffffffu, oka1);
            unsigned m1b = __ballot_sync(0xffffffffu, okb1);
            unsigned m0a = __ballot_sync(0xffffffffu, oka0);
            unsigned m0b = __ballot_sync(0xffffffffu, okb0);
            int c1a = __popc(m1a), tot1 = c1a + __popc(m1b);
            int c0a = __popc(m0a), tot0 = c0a + __popc(m0b);
            if (tot1) {
                int bpos = 0;
                if (lane == 0) bpos = atomicAdd(&scnt1, tot1);
                bpos = __shfl_sync(0xffffffffu, bpos, 0);
                if (oka1) {
                    lmin1 = min(lmin1, idxa);
                    int pos = bpos + __popc(m1a & low);
                    if (pos < CAP1) { cand1[pos] = idxa; atomicAdd(&bc1[idxa >> 9], 1); }
                }
                if (okb1) {
                    lmin1 = min(lmin1, idxb);
                    int pos = bpos + c1a + __popc(m1b & low);
                    if (pos < CAP1) { cand1[pos] = idxb; atomicAdd(&bc1[idxb >> 9], 1); }
                }
            }
            if (tot0) {
                int bpos = 0;
                if (lane == 0) bpos = atomicAdd(&scnt0, tot0);
                bpos = __shfl_sync(0xffffffffu, bpos, 0);
                if (oka0) {
                    lmin0 = min(lmin0, idxa);
                    int pos = bpos + __popc(m0a & low);
                    if (pos < CAP0) { cand0[pos] = idxa; atomicAdd(&bc0[idxa >> 9], 1); }
                }
                if (okb0) {
                    lmin0 = min(lmin0, idxb);
                    int pos = bpos + c0a + __popc(m0b & low);
                    if (pos < CAP0) { cand0[pos] = idxb; atomicAdd(&bc0[idxb >> 9], 1); }
                }
            }
        }
    }
    #pragma unroll
    for (int d = 16; d; d >>= 1) {
        lmin1 = min(lmin1, __shfl_xor_sync(0xffffffffu, lmin1, d));
        lmin0 = min(lmin0, __shfl_xor_sync(0xffffffffu, lmin0, d));
    }
    if (lane == 0) {
        atomicMin(&slmin1, lmin1);
        atomicMin(&slmin0, lmin0);
    }
    __syncthreads();

    if (wid == 0) {
        int n = select_k(cand1, min(scnt1, CAP1), bc1, sel2a, fin1, NS1, lane, low);
        if (lane == 0) m1n_s = n;
    } else if (wid == 1) {
        int n = select_k(cand0, min(scnt0, CAP0), bc0, sel2b, fin0, NS0, lane, low);
        if (lane == 0) m0n_s = n;
    }
    __syncthreads();

    if (wid == 0) {   // scale-1 grouping
        int m1n = m1n_s;
        int sidx = q * NS1 + lane;
        float g[19];
        if (m1n == 0) {
            #pragma unroll
            for (int c = 0; c < 19; c++) g[c] = 0.f;
        } else {
            int id = (lane < m1n) ? fin1[lane] : slmin1;
            float4 p = d_pts4[nbase + id];
            g[0] = p.x - qx; g[1] = p.y - qy; g[2] = p.z - qz;
            const float4* f = (const float4*)(feat + (size_t)(nbase + id) * CINF);
            float4 f0 = f[0], f1 = f[1], f2 = f[2], f3 = f[3];
            g[3]=f0.x; g[4]=f0.y; g[5]=f0.z; g[6]=f0.w;
            g[7]=f1.x; g[8]=f1.y; g[9]=f1.z; g[10]=f1.w;
            g[11]=f2.x; g[12]=f2.y; g[13]=f2.z; g[14]=f2.w;
            g[15]=f3.x; g[16]=f3.y; g[17]=f3.z; g[18]=f3.w;
        }
        #pragma unroll
        for (int c = 0; c < 19; c++) d_g1[c * NT1 + sidx] = g[c];
    } else if (wid == 1 && lane < NS0) {   // scale-0 grouping
        int m0n = m0n_s;
        int sidx = q * NS0 + lane;
        float g[19];
        if (m0n == 0) {
            #pragma unroll
            for (int c = 0; c < 19; c++) g[c] = 0.f;
        } else {
            int id = (lane < m0n) ? fin0[lane] : slmin0;
            float4 p = d_pts4[nbase + id];
            g[0] = p.x - qx; g[1] = p.y - qy; g[2] = p.z - qz;
            const float4* f = (const float4*)(feat + (size_t)(nbase + id) * CINF);
            float4 f0 = f[0], f1 = f[1], f2 = f[2], f3 = f[3];
            g[3]=f0.x; g[4]=f0.y; g[5]=f0.z; g[6]=f0.w;
            g[7]=f1.x; g[8]=f1.y; g[9]=f1.z; g[10]=f1.w;
            g[11]=f2.x; g[12]=f2.y; g[13]=f2.z; g[14]=f2.w;
            g[15]=f3.x; g[16]=f3.y; g[17]=f3.z; g[18]=f3.w;
        }
        #pragma unroll
        for (int c = 0; c < 19; c++) d_g0[c * NT0 + sidx] = g[c];
    }
}

// ---------------- layer-1 GEMV body (SPT=2, writes xa + stats) -------------
template<int CIN, int CINP, int COUT>
__device__ __forceinline__ void gemv1_body(
    int bid, const float* __restrict__ in, int ntot,
    const float* __restrict__ W, float* __restrict__ out, int off,
    float* __restrict__ sW, float* __restrict__ shm, float* __restrict__ shq)
{
    for (int i = threadIdx.x; i < COUT * CINP; i += 256) {
        int o = i / CINP, c = i % CINP;
        sW[i] = (c < CIN) ? W[o * CIN + c] : 0.f;
    }
    for (int i = threadIdx.x; i < COUT; i += 256) { shm[i] = 0.f; shq[i] = 0.f; }
    __syncthreads();

    int s    = (bid * 256 + threadIdx.x) * 2;
    int lane = threadIdx.x & 31;

    float2 x[CINP];
    #pragma unroll
    for (int c = 0; c < CINP; c++)
        x[c] = (c < CIN) ? *(const float2*)&in[(size_t)c * ntot + s]
                         : make_float2(0.f, 0.f);

    const float4* sW4 = (const float4*)sW;
    #pragma unroll
    for (int o = 0; o < COUT; o++) {
        float ax = 0.f, ay = 0.f;
        #pragma unroll
        for (int c4 = 0; c4 < CINP / 4; c4++) {
            float4 wv = sW4[o * (CINP / 4) + c4];
            ax = fmaf(x[c4*4+0].x, wv.x, ax); ay = fmaf(x[c4*4+0].y, wv.x, ay);
            ax = fmaf(x[c4*4+1].x, wv.y, ax); ay = fmaf(x[c4*4+1].y, wv.y, ay);
            ax = fmaf(x[c4*4+2].x, wv.z, ax); ay = fmaf(x[c4*4+2].y, wv.z, ay);
            ax = fmaf(x[c4*4+3].x, wv.w, ax); ay = fmaf(x[c4*4+3].y, wv.w, ay);
        }
        *(float2*)&out[(size_t)o * ntot + s] = make_float2(ax, ay);
        float sm = ax + ay;
        float sq = fmaf(ax, ax, ay * ay);
        #pragma unroll
        for (int d = 16; d; d >>= 1) {
            sm += __shfl_down_sync(0xffffffffu, sm, d);
            sq += __shfl_down_sync(0xffffffffu, sq, d);
        }
        if (lane == 0) { atomicAdd(&shm[o], sm); atomicAdd(&shq[o], sq); }
    }
    __syncthreads();
    if (threadIdx.x < COUT) {
        atomicAdd(&d_scr.sum[off + threadIdx.x], (double)shm[threadIdx.x]);
        atomicAdd(&d_scr.sqs[off + threadIdx.x], (double)shq[threadIdx.x]);
    }
}

// ---------------- kernel 3: fused layer-1 GEMVs (SPT=2, 384 blocks) --------
__global__ void __launch_bounds__(256) gemv_l1_kernel(
    const float* __restrict__ w10, const float* __restrict__ w00)
{
    __shared__ __align__(16) float sW[32 * 20];
    __shared__ float shm[32], shq[32];
    if (blockIdx.x < 256)
        gemv1_body<19, 20, 32>(blockIdx.x, d_g1, NT1, w10, d_xa1, OFF_S1L1,
                               sW, shm, shq);
    else
        gemv1_body<19, 20, 16>(blockIdx.x - 256, d_g0, NT0, w00, d_xa0,
                               OFF_S0L1, sW, shm, shq);
}

// ---------------- layer-2 body: BN/ReLU in + GEMV + stats + extremals ------
// SPT=2; both samples of a thread belong to the same query (NS/2-lane groups).
template<int CIN, int COUT, int NS, int COLOFF>
__device__ __forceinline__ void gemv2_body(
    int bid, const float* __restrict__ in, int ntot,
    const float* __restrict__ W,
    const float* __restrict__ gamma_, const float* __restrict__ beta_,
    float pN, int poff, int off,
    float* __restrict__ sW, float* __restrict__ sS, float* __restrict__ sB,
    float* __restrict__ shm, float* __restrict__ shq)
{
    for (int i = threadIdx.x; i < COUT * CIN; i += 256)
        sW[i] = W[i];
    for (int i = threadIdx.x; i < COUT; i += 256) { shm[i] = 0.f; shq[i] = 0.f; }
    for (int i = threadIdx.x; i < CIN; i += 256) {
        double inv  = 1.0 / (double)pN;
        double mean = d_scr.sum[poff + i] * inv;
        double var  = d_scr.sqs[poff + i] * inv - mean * mean;
        double sc   = (double)gamma_[i] * rsqrt(var + 1e-5);
        sS[i] = (float)sc;
        sB[i] = (float)((double)beta_[i] - mean * sc);
    }
    __syncthreads();

    int s    = (bid * 256 + threadIdx.x) * 2;
    int lane = threadIdx.x & 31;
    int q    = s / NS;

    float2 x[CIN];
    #pragma unroll
    for (int c = 0; c < CIN; c++) {
        float2 v = *(const float2*)&in[(size_t)c * ntot + s];
        v.x = fmaxf(fmaf(v.x, sS[c], sB[c]), 0.f);
        v.y = fmaxf(fmaf(v.y, sS[c], sB[c]), 0.f);
        x[c] = v;
    }

    const float4* sW4 = (const float4*)sW;
    #pragma unroll
    for (int o = 0; o < COUT; o++) {
        float ax = 0.f, ay = 0.f;
        #pragma unroll
        for (int c4 = 0; c4 < CIN / 4; c4++) {
            float4 wv = sW4[o * (CIN / 4) + c4];
            ax = fmaf(x[c4*4+0].x, wv.x, ax); ay = fmaf(x[c4*4+0].y, wv.x, ay);
            ax = fmaf(x[c4*4+1].x, wv.y, ax); ay = fmaf(x[c4*4+1].y, wv.y, ay);
            ax = fmaf(x[c4*4+2].x, wv.z, ax); ay = fmaf(x[c4*4+2].y, wv.z, ay);
            ax = fmaf(x[c4*4+3].x, wv.w, ax); ay = fmaf(x[c4*4+3].y, wv.w, ay);
        }
        // stats (full-warp reduce)
        float sm = ax + ay;
        float sq = fmaf(ax, ax, ay * ay);
        #pragma unroll
        for (int d = 16; d; d >>= 1) {
            sm += __shfl_down_sync(0xffffffffu, sm, d);
            sq += __shfl_down_sync(0xffffffffu, sq, d);
        }
        if (lane == 0) { atomicAdd(&shm[o], sm); atomicAdd(&shq[o], sq); }

        // per-query extremals (segmented reduce over NS/2 lanes)
        float mx = fmaxf(ax, ay), mn = fminf(ax, ay);
        #pragma unroll
        for (int d = 1; d < NS / 2; d <<= 1) {
            mx = fmaxf(mx, __shfl_xor_sync(0xffffffffu, mx, d));
            mn = fminf(mn, __shfl_xor_sync(0xffffffffu, mn, d));
        }
        if ((lane & (NS / 2 - 1)) == 0) {
            d_mx[q * 96 + COLOFF + o] = mx;
            d_mn[q * 96 + COLOFF + o] = mn;
        }
    }
    __syncthreads();
    if (threadIdx.x < COUT) {
        atomicAdd(&d_scr.sum[off + threadIdx.x], (double)shm[threadIdx.x]);
        atomicAdd(&d_scr.sqs[off + threadIdx.x], (double)shq[threadIdx.x]);
    }
}

// ---------------- kernel 4: fused layer-2 GEMVs + extremals ----------------
// blocks [0,256): scale1. blocks [256,384): scale0. last block -> BN params.
__global__ void __launch_bounds__(256) gemv_l2_kernel(
    const float* __restrict__ w11, const float* __restrict__ g10,
    const float* __restrict__ b10,
    const float* __restrict__ w01, const float* __restrict__ g00,
    const float* __restrict__ b00,
    const float* __restrict__ g11, const float* __restrict__ b11,
    const float* __restrict__ g01, const float* __restrict__ b01)
{
    __shared__ __align__(16) float sW[64 * 32];
    __shared__ float sS[32], sB[32], shm[64], shq[64];
    __shared__ int is_last;

    if (blockIdx.x < 256)
        gemv2_body<32, 64, NS1, 32>(blockIdx.x, d_xa1, NT1, w11, g10, b10,
                                    (float)NT1, OFF_S1L1, OFF_S1L2,
                                    sW, sS, sB, shm, shq);
    else
        gemv2_body<16, 32, NS0, 0>(blockIdx.x - 256, d_xa0, NT0, w01, g00, b00,
                                   (float)NT0, OFF_S0L1, OFF_S0L2,
                                   sW, sS, sB, shm, shq);

    if (threadIdx.x == 0) {
        __threadfence();
        is_last = (atomicAdd(&d_scr.ctr2, 1u) == NB_L2 - 1);
    }
    __syncthreads();
    if (is_last && threadIdx.x < 96) {
        int t = threadIdx.x;
        int off; float pN, gam, bet;
        if (t < 32) { off = OFF_S0L2 + t; pN = (float)NT0; gam = g01[t]; bet = b01[t]; }
        else        { off = OFF_S1L2 + t - 32; pN = (float)NT1; gam = g11[t-32]; bet = b11[t-32]; }
        __threadfence();
        double inv  = 1.0 / (double)pN;
        double mean = d_scr.sum[off] * inv;
        double var  = d_scr.sqs[off] * inv - mean * mean;
        double sc   = (double)gam * rsqrt(var + 1e-5);
        d_p2s[t] = (float)sc;
        d_p2b[t] = (float)((double)bet - mean * sc);
    }
}

// ---------------- kernel 5: finalize (BN affine + ReLU on extremals) -------
__global__ void __launch_bounds__(256) finalize_kernel(int out_off,
                                                       float* __restrict__ out)
{
    int idx = blockIdx.x * 256 + threadIdx.x;
    if (idx >= NQK * 96) return;
    int col = idx % 96;
    float sc = d_p2s[col], bi = d_p2b[col];
    float v = (sc >= 0.f) ? d_mx[idx] : d_mn[idx];
    out[out_off + idx] = fmaxf(fmaf(v, sc, bi), 0.f);
}

// ---------------- launch ----------------------------------------------------
extern "C" void kernel_launch(void* const* d_in, const int* in_sizes, int n_in,
                              void* d_out, int out_size)
{
    const float* xyz  = (const float*)d_in[0];
    const float* nxyz = (const float*)d_in[2];
    const float* feat = (const float*)d_in[4];
    const float* w00 = (const float*)d_in[5];
    const float* g00 = (const float*)d_in[6];
    const float* b00 = (const float*)d_in[7];
    const float* w01 = (const float*)d_in[8];
    const float* g01 = (const float*)d_in[9];
    const float* b01 = (const float*)d_in[10];
    const float* w10 = (const float*)d_in[11];
    const float* g10 = (const float*)d_in[12];
    const float* b10 = (const float*)d_in[13];
    const float* w11 = (const float*)d_in[14];
    const float* g11 = (const float*)d_in[15];
    const float* b11 = (const float*)d_in[16];
    float* out = (float*)d_out;

    void* scr;
    cudaGetSymbolAddress(&scr, d_scr);

    int out_off = out_size - NQK * 96;
    if (out_off < 0) out_off = 0;

    cudaMemsetAsync(scr, 0, sizeof(Scratch));                       // 1

    prep_count_kernel<<<(2 * N_PERK + 255) / 256, 256>>>(xyz);      // 2
    scatter_kernel<<<(2 * N_PERK + 255) / 256, 256>>>();            // 3
    bq_block_kernel<<<NQK, 128>>>(nxyz, feat);                      // 4
    gemv_l1_kernel<<<384, 256>>>(w10, w00);                         // 5
    gemv_l2_kernel<<<384, 256>>>(w11, g10, b10, w01, g00, b00,      // 6 <- capture
                                 g11, b11, g01, b01);
    finalize_kernel<<<(NQK * 96 + 255) / 256, 256>>>(out_off, out); // 7

    if (out_off > 0)
        cudaMemcpyAsync(out, nxyz, (size_t)out_off * sizeof(float),
                        cudaMemcpyDeviceToDevice);                  // 8
}